// round 16
// baseline (speedup 1.0000x reference)
#include <cuda_runtime.h>

#define KA    9
#define HH    240
#define WW    240
#define HW    57600
#define NTOT  518400
#define WK    2160
#define PRE   6000
#define POST  300
#define CAP   8192
#define NB    65536
#define MROW  2048            // matrix-covered candidates
#define MW    64              // words per row (MROW/32)

__device__ __align__(16) unsigned  g_hist[NB];    // zero invariant
__device__ __align__(16) unsigned  g_base[NB];    // fully rewritten each launch
__device__ unsigned                g_tick0;       // zero invariant (self-reset)
__device__ int                     g_bound;
__device__ int                     g_n;
__device__ unsigned long long      g_cand[CAP];
__device__ unsigned                g_rank[CAP];   // fully rewritten (non-atomic)
__device__ float                   g_sc[PRE];
__device__ float4                  g_boxes[PRE];
__device__ __align__(16) unsigned  g_mat[MROW * MW];

__device__ __forceinline__ unsigned mono(float f) {
    unsigned b = __float_as_uint(f);
    return (b & 0x80000000u) ? ~b : (b | 0x80000000u);
}
__device__ __forceinline__ float unmono(unsigned m) {
    unsigned b = (m & 0x80000000u) ? (m ^ 0x80000000u) : ~m;
    return __uint_as_float(b);
}
__device__ __forceinline__ float box_area(float4 b) {
    return __fmul_rn(fmaxf(b.z - b.x, 0.0f), fmaxf(b.w - b.y, 0.0f));
}
// exact formula (rel_err 0.0 lineage)
__device__ __forceinline__ bool iou_gt(float4 a, float areaA, float4 b, float areaB) {
    float lx = fmaxf(a.x, b.x);
    float ly = fmaxf(a.y, b.y);
    float rx = fminf(a.z, b.z);
    float ry = fminf(a.w, b.w);
    float iw = fmaxf(rx - lx, 0.0f);
    float ih = fmaxf(ry - ly, 0.0f);
    float inter = __fmul_rn(iw, ih);
    float uni = fmaxf(__fsub_rn(__fadd_rn(areaA, areaB), inter), 1e-9f);
    return __fdiv_rn(inter, uni) > 0.6f;
}
// early-out: iw<=0 or ih<=0 => inter=0 => IoU=0, never >0.6 (exact)
__device__ __forceinline__ bool iou_gt_eo(float4 a, float areaA, float4 b) {
    float lx = fmaxf(a.x, b.x);
    float ly = fmaxf(a.y, b.y);
    float rx = fminf(a.z, b.z);
    float ry = fminf(a.w, b.w);
    float iw = rx - lx;
    float ih = ry - ly;
    if (iw <= 0.0f || ih <= 0.0f) return false;
    float inter = __fmul_rn(iw, ih);
    float areaB = box_area(b);
    float uni = fmaxf(__fsub_rn(__fadd_rn(areaA, areaB), inter), 1e-9f);
    return __fdiv_rn(inter, uni) > 0.6f;
}
__device__ __forceinline__ void cp16(unsigned dst, const void* src) {
    asm volatile("cp.async.cg.shared.global [%0], [%1], 16;" :: "r"(dst), "l"(src));
}

// ---- 1: histogram (float4); last block: boundary + above-count table -----
__global__ __launch_bounds__(1024) void k_hist(const float* __restrict__ cls) {
    int t = blockIdx.x * 1024 + threadIdx.x;
    if (t < NTOT / 4) {
        int e = t * 4;
        int k = e / HW;
        int r = e - k * HW;
        const float4 v = *(const float4*)&cls[(2 * k) * HW + r];
        atomicAdd(&g_hist[mono(v.x) >> 16], 1u);
        atomicAdd(&g_hist[mono(v.y) >> 16], 1u);
        atomicAdd(&g_hist[mono(v.z) >> 16], 1u);
        atomicAdd(&g_hist[mono(v.w) >> 16], 1u);
    }
    __shared__ bool last;
    if (threadIdx.x == 0)
        last = (atomicAdd(&g_tick0, 1u) == gridDim.x - 1);
    __syncthreads();
    if (!last) return;
    if (threadIdx.x == 0) g_tick0 = 0u;          // restore invariant (all arrived)

    // boundary bucket + g_base = "#keys in strictly higher buckets" (R12-validated)
    __shared__ int ws[32];
    int tid = threadIdx.x;
    const uint4* h4 = (const uint4*)g_hist;
    int base4 = tid * 16;
    int sum = 0;
    #pragma unroll
    for (int j = 0; j < 16; ++j) {
        uint4 v = __ldcg(&h4[base4 + j]);
        sum += (int)(v.x + v.y + v.z + v.w);
    }
    int lane = tid & 31, warp = tid >> 5;
    int sfx = sum;
    #pragma unroll
    for (int d = 1; d < 32; d <<= 1) {
        int v = __shfl_down_sync(0xFFFFFFFFu, sfx, d);
        if (lane < 32 - d) sfx += v;
    }
    if (lane == 0) ws[warp] = sfx;
    __syncthreads();
    int tail = 0;
    for (int w2 = warp + 1; w2 < 32; ++w2) tail += ws[w2];
    int St = sfx + tail;                         // suffix incl this thread's 64 buckets

    uint4* b4 = (uint4*)g_base;
    int run_incl = St;
    #pragma unroll
    for (int j = 0; j < 16; ++j) {
        uint4 v = __ldcg(&h4[base4 + j]);
        uint4 o;
        int h0 = (int)v.x, h1 = (int)v.y, h2 = (int)v.z, h3 = (int)v.w;
        o.x = (unsigned)(run_incl - h0);
        if (run_incl >= PRE && run_incl - h0 < PRE) { g_bound = tid * 64 + j * 4 + 0; g_n = run_incl; }
        run_incl -= h0;
        o.y = (unsigned)(run_incl - h1);
        if (run_incl >= PRE && run_incl - h1 < PRE) { g_bound = tid * 64 + j * 4 + 1; g_n = run_incl; }
        run_incl -= h1;
        o.z = (unsigned)(run_incl - h2);
        if (run_incl >= PRE && run_incl - h2 < PRE) { g_bound = tid * 64 + j * 4 + 2; g_n = run_incl; }
        run_incl -= h2;
        o.w = (unsigned)(run_incl - h3);
        if (run_incl >= PRE && run_incl - h3 < PRE) { g_bound = tid * 64 + j * 4 + 3; g_n = run_incl; }
        run_incl -= h3;
        b4[base4 + j] = o;
    }
}

// ---- 2: compact into per-bucket slot ranges -----------------------------
__global__ void k_compact(const float* __restrict__ cls) {
    int i = blockIdx.x * blockDim.x + threadIdx.x;
    if (i >= NTOT) return;
    int k = i / HW;
    int r = i - k * HW;
    float s = __ldg(&cls[(2 * k) * HW + r]);
    unsigned key = mono(s);
    unsigned b = key >> 16;
    if ((int)b >= g_bound) {
        unsigned slot = atomicAdd(&g_base[b], 1u);    // [above(b), above(b)+nb)
        if (slot < CAP)
            g_cand[slot] = ((unsigned long long)key << 20)
                         | (unsigned)((~(unsigned)i) & 0xFFFFFu);
    }
}

// ---- 3: exact rank = bucket_start + in-bucket count (8 lanes/candidate) --
__global__ void k_rank() {
    int t = blockIdx.x * blockDim.x + threadIdx.x;    // t < CAP*8
    int i = t >> 3, s = t & 7;
    int n = g_n; if (n > CAP) n = CAP;
    bool active = (i < n);
    int cnt = 0, bstart = 0;
    unsigned long long cv = 0ULL;
    if (active) {
        cv = __ldg(&g_cand[i]);
        unsigned b = (unsigned)(cv >> 36);            // key >> 16
        int bend = (int)__ldg(&g_base[b]);            // above(b) + nb
        if (bend > CAP) bend = CAP;
        bstart = bend - (int)__ldg(&g_hist[b]);
        if (bstart < 0) bstart = 0;
        int len = bend - bstart;
        int seg = (len + 7) >> 3;
        int j0 = bstart + s * seg;
        int j1 = j0 + seg; if (j1 > bend) j1 = bend;
        for (int j = j0; j < j1; ++j)
            cnt += (__ldg(&g_cand[j]) > cv);
    }
    // reduce across the 8-lane subgroup (lanes aligned: 8 | 32)
    cnt += __shfl_down_sync(0xFFFFFFFFu, cnt, 4, 8);
    cnt += __shfl_down_sync(0xFFFFFFFFu, cnt, 2, 8);
    cnt += __shfl_down_sync(0xFFFFFFFFu, cnt, 1, 8);
    if (active && s == 0) g_rank[i] = (unsigned)(bstart + cnt);   // absolute rank
}

// ---- 4: scatter by rank + box decode — (candidate, corner) threads -------
__global__ void k_scatter(const float* __restrict__ deltas,
                          const float* __restrict__ anchors) {
    int t = blockIdx.x * blockDim.x + threadIdx.x;    // t < CAP*4
    int i = t >> 2, q = t & 3;
    int n = g_n; if (n > CAP) n = CAP;
    if (i >= n) return;
    unsigned r = g_rank[i];
    if (r >= PRE) return;
    unsigned long long cv = g_cand[i];
    int idx = (int)((~(unsigned)cv) & 0xFFFFFu);
    if (q == 0) g_sc[r] = unmono((unsigned)(cv >> 20));
    int hp = idx / WK;
    int tt = idx - hp * WK;
    int wp = tt / KA;
    int kp = tt - wp * KA;
    int F   = ((kp * 4 + q) * HH + hp) * WW + wp;
    int j2  = F & 3;
    int F4  = F >> 2;
    int k2  = F4 % KA;
    int rem = F4 / KA;
    int w2  = rem % WW;
    int h2  = rem / WW;
    float a = __ldg(&anchors[((h2 * WW + w2) * KA + k2) * 4 + j2]);
    float d = __ldg(&deltas[(k2 * 4 + j2) * HW + h2 * WW + w2]);
    ((float*)&g_boxes[r])[q] = fminf(fmaxf(a + d, 0.0f), 1920.0f);
}

// ---- 5: upper-triangle suppression bit-matrix + hist reset ---------------
__global__ __launch_bounds__(1024) void k_mat() {
    int i = blockIdx.x;
    int tid = threadIdx.x;
    float4 bi = g_boxes[i];
    float  ai = box_area(bi);
    int j0 = tid;
    int j1 = j0 + 1024;
    bool s0 = (j0 > i) && iou_gt_eo(bi, ai, g_boxes[j0]);
    bool s1 = (j1 > i) && iou_gt_eo(bi, ai, g_boxes[j1]);
    unsigned w0 = __ballot_sync(0xFFFFFFFFu, s0);
    unsigned w1 = __ballot_sync(0xFFFFFFFFu, s1);
    if ((j0 & 31) == 0) {
        int w = j0 >> 5;
        g_mat[i * MW + w]      = w0;
        g_mat[i * MW + w + 32] = w1;
    }
    // hist reset on dead data: 2048 blocks x 32 = NB exactly
    if (tid < 32) g_hist[i * 32 + tid] = 0u;
}

// ---- 6: warp-serial matrix sweep (4-deep cp.async) + fallback + output ---
__global__ __launch_bounds__(1024) void k_nms(float* __restrict__ out) {
    __shared__ __align__(16) unsigned rowbuf[4 * 32 * MW];   // 4 x 8 KB ring
    __shared__ int      s_kidx[POST];
    __shared__ int      s_nk;
    __shared__ float4   kbox[POST];
    __shared__ float    karea[POST];
    __shared__ float4   bb[32];
    __shared__ float    ba[32];
    __shared__ unsigned s_sup;
    int tid = threadIdx.x, lane = tid & 31, warp = tid >> 5;

    if (warp == 0) {
        unsigned sbase = (unsigned)__cvta_generic_to_shared(rowbuf) + lane * 16;
        unsigned m0 = 0u, m1 = 0u;        // lane owns future-mask words 2*lane, 2*lane+1
        int nk = 0;

        #pragma unroll
        for (int p = 0; p < 3; ++p) {     // prime chunks 0..2
            const uint4* src = (const uint4*)&g_mat[(p << 5) * MW];
            unsigned d = sbase + p * 8192;
            #pragma unroll
            for (int q = 0; q < 16; ++q) cp16(d + q * 512, src + lane + 32 * q);
            asm volatile("cp.async.commit_group;");
        }
        for (int c = 0; c < MW && nk < POST; ++c) {
            if (c + 3 < MW) {
                const uint4* src = (const uint4*)&g_mat[((c + 3) << 5) * MW];
                unsigned d = sbase + ((c + 3) & 3) * 8192;
                #pragma unroll
                for (int q = 0; q < 16; ++q) cp16(d + q * 512, src + lane + 32 * q);
            }
            asm volatile("cp.async.commit_group;");   // uniform group count
            asm volatile("cp.async.wait_group 3;");
            __syncwarp();
            const unsigned* rb = rowbuf + (c & 3) * (32 * MW);

            unsigned cur = __shfl_sync(0xFFFFFFFFu, (c & 1) ? m1 : m0, c >> 1);
            unsigned alive = ~cur;
            while (alive && nk < POST) {
                int l = __ffs(alive) - 1;
                if (lane == 0) s_kidx[nk] = (c << 5) + l;
                ++nk;
                cur |= rb[l * MW + c];                 // broadcast LDS
                m0  |= rb[l * MW + 2 * lane];
                m1  |= rb[l * MW + 2 * lane + 1];
                alive = (~cur) & ~((2u << l) - 1u);    // unsuppressed, index > l
            }
            __syncwarp();
        }
        asm volatile("cp.async.wait_group 0;");
        if (lane == 0) s_nk = nk;
    }
    __syncthreads();
    int nk = s_nk;

    // fallback past MROW (rare): lazy 32-wide batches
    if (nk < POST) {
        for (int p = tid; p < nk; p += 1024) {
            float4 b = g_boxes[s_kidx[p]];
            kbox[p] = b; karea[p] = box_area(b);
        }
        if (tid == 0) s_sup = 0u;
        __syncthreads();
        for (int base = MROW; base < PRE && nk < POST; base += 32) {
            int rem = PRE - base; if (rem > 32) rem = 32;
            if (tid < rem) {
                float4 b = g_boxes[base + tid];
                bb[tid] = b; ba[tid] = box_area(b);
            }
            __syncthreads();
            int total = nk << 5;
            for (int idx2 = tid; idx2 < total; idx2 += 1024) {
                int cc = idx2 & 31;
                if (cc < rem && !((s_sup >> cc) & 1u)) {
                    int k = idx2 >> 5;
                    if (iou_gt(kbox[k], karea[k], bb[cc], ba[cc]))
                        atomicOr(&s_sup, 1u << cc);
                }
            }
            __syncthreads();
            if (tid < 32) {
                unsigned valid = (rem >= 32) ? 0xFFFFFFFFu : ((1u << rem) - 1u);
                unsigned alive = (~s_sup) & valid;
                float4 myb = bb[(lane < rem) ? lane : 0];
                float  mya = ba[(lane < rem) ? lane : 0];
                int nk2 = nk;
                while (alive && nk2 < POST) {
                    int l = __ffs((int)alive) - 1;
                    alive &= ~(1u << l);
                    float4 kb;
                    kb.x = __shfl_sync(0xFFFFFFFFu, myb.x, l);
                    kb.y = __shfl_sync(0xFFFFFFFFu, myb.y, l);
                    kb.z = __shfl_sync(0xFFFFFFFFu, myb.z, l);
                    kb.w = __shfl_sync(0xFFFFFFFFu, myb.w, l);
                    float ka_ = __shfl_sync(0xFFFFFFFFu, mya, l);
                    if (lane == 0) { kbox[nk2] = kb; karea[nk2] = ka_; s_kidx[nk2] = base + l; }
                    ++nk2;
                    if (nk2 >= POST) break;
                    bool sup = false;
                    if (alive & (1u << lane)) sup = iou_gt(kb, ka_, myb, mya);
                    alive &= ~__ballot_sync(0xFFFFFFFFu, sup);
                }
                if (lane == 0) { s_nk = nk2; s_sup = 0u; }
            }
            __syncthreads();
            nk = s_nk;
        }
    }

    // output [1, POST, 5]; pad with candidate 0 (nonzero fill_value=0)
    for (int p = tid; p < POST; p += 1024) {
        int q = (p < nk) ? s_kidx[p] : 0;
        float4 b = g_boxes[q];
        out[p * 5 + 0] = g_sc[q];
        out[p * 5 + 1] = b.x;
        out[p * 5 + 2] = b.y;
        out[p * 5 + 3] = b.z;
        out[p * 5 + 4] = b.w;
    }
}

// ---------------------------------------------------------------- launcher
extern "C" void kernel_launch(void* const* d_in, const int* in_sizes, int n_in,
                              void* d_out, int out_size) {
    const float* cls     = (const float*)d_in[0];
    const float* deltas  = (const float*)d_in[1];
    const float* anchors = (const float*)d_in[2];
    float* out = (float*)d_out;

    k_hist   <<<(NTOT / 4 + 1023) / 1024, 1024>>>(cls);
    k_compact<<<(NTOT + 255) / 256, 256>>>(cls);
    k_rank   <<<(CAP * 8 + 255) / 256, 256>>>();
    k_scatter<<<(CAP * 4 + 255) / 256, 256>>>(deltas, anchors);
    k_mat    <<<MROW, 1024>>>();
    k_nms    <<<1, 1024>>>(out);
}

// round 17
// speedup vs baseline: 1.1219x; 1.1219x over previous
#include <cuda_runtime.h>

#define KA    9
#define HH    240
#define WW    240
#define HW    57600
#define NTOT  518400
#define WK    2160
#define PRE   6000
#define POST  300
#define CAP   8192
#define NB    65536
#define CHK   9
#define MROW  2048            // matrix-covered candidates
#define MW    64              // words per row (MROW/32)

__device__ __align__(16) unsigned  g_hist[NB];    // zero invariant
__device__ unsigned                g_cnt;         // zero invariant
__device__ unsigned                g_rank[CAP];   // zero invariant
__device__ int                     g_bound;
__device__ unsigned long long      g_cand[CAP];
__device__ float                   g_sc[PRE];
__device__ float4                  g_boxes[PRE];
__device__ __align__(16) unsigned  g_mat[MROW * MW];

__device__ __forceinline__ unsigned mono(float f) {
    unsigned b = __float_as_uint(f);
    return (b & 0x80000000u) ? ~b : (b | 0x80000000u);
}
__device__ __forceinline__ float unmono(unsigned m) {
    unsigned b = (m & 0x80000000u) ? (m ^ 0x80000000u) : ~m;
    return __uint_as_float(b);
}
__device__ __forceinline__ float box_area(float4 b) {
    return __fmul_rn(fmaxf(b.z - b.x, 0.0f), fmaxf(b.w - b.y, 0.0f));
}
// exact formula (rel_err 0.0 lineage)
__device__ __forceinline__ bool iou_gt(float4 a, float areaA, float4 b, float areaB) {
    float lx = fmaxf(a.x, b.x);
    float ly = fmaxf(a.y, b.y);
    float rx = fminf(a.z, b.z);
    float ry = fminf(a.w, b.w);
    float iw = fmaxf(rx - lx, 0.0f);
    float ih = fmaxf(ry - ly, 0.0f);
    float inter = __fmul_rn(iw, ih);
    float uni = fmaxf(__fsub_rn(__fadd_rn(areaA, areaB), inter), 1e-9f);
    return __fdiv_rn(inter, uni) > 0.6f;
}
// early-out: iw<=0 or ih<=0 => inter=0 => IoU=0, never >0.6 (exact)
__device__ __forceinline__ bool iou_gt_eo(float4 a, float areaA, float4 b) {
    float lx = fmaxf(a.x, b.x);
    float ly = fmaxf(a.y, b.y);
    float rx = fminf(a.z, b.z);
    float ry = fminf(a.w, b.w);
    float iw = rx - lx;
    float ih = ry - ly;
    if (iw <= 0.0f || ih <= 0.0f) return false;
    float inter = __fmul_rn(iw, ih);
    float areaB = box_area(b);
    float uni = fmaxf(__fsub_rn(__fadd_rn(areaA, areaB), inter), 1e-9f);
    return __fdiv_rn(inter, uni) > 0.6f;
}
__device__ __forceinline__ void cp16(unsigned dst, const void* src) {
    asm volatile("cp.async.cg.shared.global [%0], [%1], 16;" :: "r"(dst), "l"(src));
}

// ---- 1: scores -> 64K-bucket histogram (float4) -------------------------
__global__ void k_hist(const float* __restrict__ cls) {
    int t = blockIdx.x * blockDim.x + threadIdx.x;
    if (t >= NTOT / 4) return;
    int e = t * 4;
    int k = e / HW;
    int r = e - k * HW;
    const float4 v = *(const float4*)&cls[(2 * k) * HW + r];
    atomicAdd(&g_hist[mono(v.x) >> 16], 1u);
    atomicAdd(&g_hist[mono(v.y) >> 16], 1u);
    atomicAdd(&g_hist[mono(v.z) >> 16], 1u);
    atomicAdd(&g_hist[mono(v.w) >> 16], 1u);
}

// ---- 2: boundary bucket of rank PRE -------------------------------------
__global__ __launch_bounds__(1024) void k_bound() {
    cudaGridDependencySynchronize();
    __shared__ int ws[32];
    int tid = threadIdx.x;
    const uint4* h4 = (const uint4*)g_hist;
    int base4 = tid * 16;
    int sum = 0;
    #pragma unroll
    for (int j = 0; j < 16; ++j) {
        uint4 v = h4[base4 + j];
        sum += (int)(v.x + v.y + v.z + v.w);
    }
    int lane = tid & 31, warp = tid >> 5;
    int sfx = sum;
    #pragma unroll
    for (int d = 1; d < 32; d <<= 1) {
        int v = __shfl_down_sync(0xFFFFFFFFu, sfx, d);
        if (lane < 32 - d) sfx += v;
    }
    if (lane == 0) ws[warp] = sfx;
    __syncthreads();
    int tail = 0;
    for (int w2 = warp + 1; w2 < 32; ++w2) tail += ws[w2];
    int St  = sfx + tail;
    int Snx = St - sum;
    if (St >= PRE && Snx < PRE) {
        int running = Snx;
        int base = tid * 64;
        int B = base;
        for (int j = 63; j >= 0; --j) {
            running += (int)g_hist[base + j];
            if (running >= PRE) { B = base + j; break; }
        }
        g_bound = B;
    }
}

// ---- 3: compact candidates >= bound -------------------------------------
__global__ void k_compact(const float* __restrict__ cls) {
    cudaGridDependencySynchronize();
    int i = blockIdx.x * blockDim.x + threadIdx.x;
    if (i >= NTOT) return;
    int k = i / HW;
    int r = i - k * HW;
    float s = __ldg(&cls[(2 * k) * HW + r]);
    unsigned key = mono(s);
    if ((int)(key >> 16) >= g_bound) {
        unsigned pos = atomicAdd(&g_cnt, 1u);
        if (pos < CAP)
            g_cand[pos] = ((unsigned long long)key << 20)
                        | (unsigned)((~(unsigned)i) & 0xFFFFFu);
    }
}

// ---- 4: exact descending ranks by counting (144 tile blocks) ------------
__global__ __launch_bounds__(1024) void k_rank() {
    cudaGridDependencySynchronize();
    __shared__ unsigned long long sk[1024];
    unsigned n = g_cnt; if (n > CAP) n = CAP;
    int csz = ((int)n + CHK - 1) / CHK;
    int w = blockIdx.x;
    int g = w / CHK, c = w % CHK;
    int c0 = c * csz;
    int c1 = c0 + csz; if (c1 > (int)n) c1 = (int)n;
    int clen = c1 - c0;
    for (int j = threadIdx.x; j < clen; j += 1024) sk[j] = g_cand[c0 + j];
    __syncthreads();
    int ci = g * 512 + (threadIdx.x & 511);
    int h  = threadIdx.x >> 9;
    if (ci < (int)n && clen > 0) {
        unsigned long long my = g_cand[ci];
        int half = (clen + 1) >> 1;
        int j0 = h * half;
        int j1 = j0 + half; if (j1 > clen) j1 = clen;
        int cnt = 0;
        #pragma unroll 8
        for (int j = j0; j < j1; ++j) cnt += (sk[j] > my);
        if (cnt) atomicAdd(&g_rank[ci], (unsigned)cnt);
    }
}

// ---- 5: scatter by rank + box decode — (candidate, corner) threads -------
__global__ void k_scatter(const float* __restrict__ deltas,
                          const float* __restrict__ anchors) {
    cudaGridDependencySynchronize();
    int t = blockIdx.x * blockDim.x + threadIdx.x;
    int i = t >> 2, q = t & 3;
    unsigned n = g_cnt; if (n > CAP) n = CAP;
    if (i >= (int)n) return;
    unsigned r = g_rank[i];
    if (r >= PRE) return;
    unsigned long long cv = g_cand[i];
    int idx = (int)((~(unsigned)cv) & 0xFFFFFu);
    if (q == 0) g_sc[r] = unmono((unsigned)(cv >> 20));
    int hp = idx / WK;
    int tt = idx - hp * WK;
    int wp = tt / KA;
    int kp = tt - wp * KA;
    int F   = ((kp * 4 + q) * HH + hp) * WW + wp;
    int j2  = F & 3;
    int F4  = F >> 2;
    int k2  = F4 % KA;
    int rem = F4 / KA;
    int w2  = rem % WW;
    int h2  = rem / WW;
    float a = __ldg(&anchors[((h2 * WW + w2) * KA + k2) * 4 + j2]);
    float d = __ldg(&deltas[(k2 * 4 + j2) * HW + h2 * WW + w2]);
    ((float*)&g_boxes[r])[q] = fminf(fmaxf(a + d, 0.0f), 1920.0f);
}

// ---- 6: upper-triangle suppression bit-matrix + invariant resets ---------
__global__ __launch_bounds__(1024) void k_mat() {
    cudaGridDependencySynchronize();
    int i = blockIdx.x;
    int tid = threadIdx.x;
    float4 bi = g_boxes[i];
    float  ai = box_area(bi);
    int j0 = tid;
    int j1 = j0 + 1024;
    bool s0 = (j0 > i) && iou_gt_eo(bi, ai, g_boxes[j0]);
    bool s1 = (j1 > i) && iou_gt_eo(bi, ai, g_boxes[j1]);
    unsigned w0 = __ballot_sync(0xFFFFFFFFu, s0);
    unsigned w1 = __ballot_sync(0xFFFFFFFFu, s1);
    if ((j0 & 31) == 0) {
        int w = j0 >> 5;
        g_mat[i * MW + w]      = w0;
        g_mat[i * MW + w + 32] = w1;
    }
    // invariant resets on dead data: 2048 blocks x 32 = NB; x4 = CAP
    if (tid < 32)                      g_hist[i * 32 + tid] = 0u;
    else if (tid < 36)                 g_rank[i * 4 + (tid - 32)] = 0u;
    else if (tid == 36 && i == 0)      g_cnt = 0u;
}

// ---- 7: warp-serial matrix sweep (4-deep cp.async) + fallback + output ---
__global__ __launch_bounds__(1024) void k_nms(float* __restrict__ out) {
    cudaGridDependencySynchronize();
    __shared__ __align__(16) unsigned rowbuf[4 * 32 * MW];   // 4 x 8 KB ring
    __shared__ int      s_kidx[POST];
    __shared__ int      s_nk;
    __shared__ float4   kbox[POST];
    __shared__ float    karea[POST];
    __shared__ float4   bb[32];
    __shared__ float    ba[32];
    __shared__ unsigned s_sup;
    int tid = threadIdx.x, lane = tid & 31, warp = tid >> 5;

    if (warp == 0) {
        unsigned sbase = (unsigned)__cvta_generic_to_shared(rowbuf) + lane * 16;
        unsigned m0 = 0u, m1 = 0u;        // lane owns future-mask words 2*lane, 2*lane+1
        int nk = 0;

        #pragma unroll
        for (int p = 0; p < 3; ++p) {     // prime chunks 0..2
            const uint4* src = (const uint4*)&g_mat[(p << 5) * MW];
            unsigned d = sbase + p * 8192;
            #pragma unroll
            for (int q = 0; q < 16; ++q) cp16(d + q * 512, src + lane + 32 * q);
            asm volatile("cp.async.commit_group;");
        }
        for (int c = 0; c < MW && nk < POST; ++c) {
            if (c + 3 < MW) {
                const uint4* src = (const uint4*)&g_mat[((c + 3) << 5) * MW];
                unsigned d = sbase + ((c + 3) & 3) * 8192;
                #pragma unroll
                for (int q = 0; q < 16; ++q) cp16(d + q * 512, src + lane + 32 * q);
            }
            asm volatile("cp.async.commit_group;");   // uniform group count
            asm volatile("cp.async.wait_group 3;");
            __syncwarp();
            const unsigned* rb = rowbuf + (c & 3) * (32 * MW);

            unsigned cur = __shfl_sync(0xFFFFFFFFu, (c & 1) ? m1 : m0, c >> 1);
            unsigned alive = ~cur;
            while (alive && nk < POST) {
                int l = __ffs(alive) - 1;
                if (lane == 0) s_kidx[nk] = (c << 5) + l;
                ++nk;
                cur |= rb[l * MW + c];                 // broadcast LDS
                m0  |= rb[l * MW + 2 * lane];
                m1  |= rb[l * MW + 2 * lane + 1];
                alive = (~cur) & ~((2u << l) - 1u);    // unsuppressed, index > l
            }
            __syncwarp();
        }
        asm volatile("cp.async.wait_group 0;");
        if (lane == 0) s_nk = nk;
    }
    __syncthreads();
    int nk = s_nk;

    // fallback past MROW (rare): lazy 32-wide batches
    if (nk < POST) {
        for (int p = tid; p < nk; p += 1024) {
            float4 b = g_boxes[s_kidx[p]];
            kbox[p] = b; karea[p] = box_area(b);
        }
        if (tid == 0) s_sup = 0u;
        __syncthreads();
        for (int base = MROW; base < PRE && nk < POST; base += 32) {
            int rem = PRE - base; if (rem > 32) rem = 32;
            if (tid < rem) {
                float4 b = g_boxes[base + tid];
                bb[tid] = b; ba[tid] = box_area(b);
            }
            __syncthreads();
            int total = nk << 5;
            for (int idx2 = tid; idx2 < total; idx2 += 1024) {
                int cc = idx2 & 31;
                if (cc < rem && !((s_sup >> cc) & 1u)) {
                    int k = idx2 >> 5;
                    if (iou_gt(kbox[k], karea[k], bb[cc], ba[cc]))
                        atomicOr(&s_sup, 1u << cc);
                }
            }
            __syncthreads();
            if (tid < 32) {
                unsigned valid = (rem >= 32) ? 0xFFFFFFFFu : ((1u << rem) - 1u);
                unsigned alive = (~s_sup) & valid;
                float4 myb = bb[(lane < rem) ? lane : 0];
                float  mya = ba[(lane < rem) ? lane : 0];
                int nk2 = nk;
                while (alive && nk2 < POST) {
                    int l = __ffs((int)alive) - 1;
                    alive &= ~(1u << l);
                    float4 kb;
                    kb.x = __shfl_sync(0xFFFFFFFFu, myb.x, l);
                    kb.y = __shfl_sync(0xFFFFFFFFu, myb.y, l);
                    kb.z = __shfl_sync(0xFFFFFFFFu, myb.z, l);
                    kb.w = __shfl_sync(0xFFFFFFFFu, myb.w, l);
                    float ka_ = __shfl_sync(0xFFFFFFFFu, mya, l);
                    if (lane == 0) { kbox[nk2] = kb; karea[nk2] = ka_; s_kidx[nk2] = base + l; }
                    ++nk2;
                    if (nk2 >= POST) break;
                    bool sup = false;
                    if (alive & (1u << lane)) sup = iou_gt(kb, ka_, myb, mya);
                    alive &= ~__ballot_sync(0xFFFFFFFFu, sup);
                }
                if (lane == 0) { s_nk = nk2; s_sup = 0u; }
            }
            __syncthreads();
            nk = s_nk;
        }
    }

    // output [1, POST, 5]; pad with candidate 0 (nonzero fill_value=0)
    for (int p = tid; p < POST; p += 1024) {
        int q = (p < nk) ? s_kidx[p] : 0;
        float4 b = g_boxes[q];
        out[p * 5 + 0] = g_sc[q];
        out[p * 5 + 1] = b.x;
        out[p * 5 + 2] = b.y;
        out[p * 5 + 3] = b.z;
        out[p * 5 + 4] = b.w;
    }
}

// ---------------------------------------------------------------- launcher
template <typename K, typename... Args>
static void launch_pdl(K kern, dim3 grid, dim3 block, Args... args) {
    cudaLaunchConfig_t cfg = {};
    cfg.gridDim = grid;
    cfg.blockDim = block;
    cfg.dynamicSmemBytes = 0;
    cfg.stream = 0;
    cudaLaunchAttribute attr[1];
    attr[0].id = cudaLaunchAttributeProgrammaticStreamSerialization;
    attr[0].val.programmaticStreamSerializationAllowed = 1;
    cfg.attrs = attr;
    cfg.numAttrs = 1;
    cudaLaunchKernelEx(&cfg, kern, args...);
}

extern "C" void kernel_launch(void* const* d_in, const int* in_sizes, int n_in,
                              void* d_out, int out_size) {
    const float* cls     = (const float*)d_in[0];
    const float* deltas  = (const float*)d_in[1];
    const float* anchors = (const float*)d_in[2];
    float* out = (float*)d_out;

    k_hist<<<(NTOT / 4 + 255) / 256, 256>>>(cls);
    launch_pdl(k_bound,   dim3(1),                        dim3(1024));
    launch_pdl(k_compact, dim3((NTOT + 255) / 256),       dim3(256), cls);
    launch_pdl(k_rank,    dim3(144),                      dim3(1024));
    launch_pdl(k_scatter, dim3((CAP * 4 + 255) / 256),    dim3(256), deltas, anchors);
    launch_pdl(k_mat,     dim3(MROW),                     dim3(1024));
    launch_pdl(k_nms,     dim3(1),                        dim3(1024), out);
}